// round 10
// baseline (speedup 1.0000x reference)
#include <cuda_runtime.h>
#include <cstdint>

// Problem shapes (fixed)
#define Bq 8
#define Eq 8
#define Cq 1024
#define Iq 128
#define Oq 256
#define Tq 8192

#define NTHREADS 256
#define NCTAS 296                      // 2 persistent CTAs per SM
#define NTILES 1024                    // 2 n x 8 m x 64 be;  tile = 128 x 128
#define BK 32
#define NSTAGE 3
#define STAGE_A (128 * BK * 4)         // 16384
#define STAGE_BYTES (2 * STAGE_A)      // 32768 (A + B)
#define SMEM_BIAS  0
#define SMEM_TILES 1024
#define SMEM_TOTAL (SMEM_TILES + NSTAGE * STAGE_BYTES)   // 99328 -> 2 CTAs/SM

// Pre-rounded (cvt.rna.tf32) and P(s)-permuted weights:
// g_wprep[((e*2+nb)*128 + s)*128 + k] = rna(w[e][nb*128 + P(s)][k])
__device__ float g_wprep[2048 * 128];

// Monotonic arrival counter (never reset; generation = ticket/NCTAS).
__device__ unsigned int g_zero_ctr = 0;

__device__ __forceinline__ uint32_t smem_u32(const void* p) {
    uint32_t a;
    asm("{ .reg .u64 t; cvta.to.shared.u64 t, %1; cvt.u32.u64 %0, t; }"
        : "=r"(a) : "l"(p));
    return a;
}

__device__ __forceinline__ uint32_t f2tf32(float f) {
    uint32_t r;
    asm("cvt.rna.tf32.f32 %0, %1;" : "=r"(r) : "f"(f));
    return r;
}

#define CP_ASYNC16(saddr, gptr) \
    asm volatile("cp.async.cg.shared.global [%0], [%1], 16;" \
                 :: "r"(saddr), "l"(gptr) : "memory")

#define LDSM_X4(r0, r1, r2, r3, addr) \
    asm volatile("ldmatrix.sync.aligned.m8n8.x4.shared.b16 {%0,%1,%2,%3}, [%4];" \
                 : "=r"(r0), "=r"(r1), "=r"(r2), "=r"(r3) : "r"(addr))

#define MMA_TF32(c, a, b0, b1) \
    asm volatile("mma.sync.aligned.m16n8k8.row.col.f32.tf32.tf32.f32 " \
                 "{%0,%1,%2,%3}, {%4,%5,%6,%7}, {%8,%9}, {%0,%1,%2,%3};" \
                 : "+f"((c)[0]), "+f"((c)[1]), "+f"((c)[2]), "+f"((c)[3]) \
                 : "r"((a)[0]), "r"((a)[1]), "r"((a)[2]), "r"((a)[3]), \
                   "r"(b0), "r"(b1))

// ---------------------------------------------------------------------------
// Prep: round weights to tf32 (rna) and apply the epilogue permutation P(s).
// 1MB read + 1MB write; ~1-2us. Runs before the main kernel on stream 0.
// ---------------------------------------------------------------------------
__global__ void prep_weights(const float* __restrict__ w) {
    int t = blockIdx.x * blockDim.x + threadIdx.x;
    for (int i = t; i < 2048 * 32; i += gridDim.x * blockDim.x) {
        int row = i >> 5, c4 = i & 31;
        int e = row >> 8, nb = (row >> 7) & 1, s = row & 127;
        int ps = ((s >> 4) << 4) + ((s & 7) << 1) + ((s >> 3) & 1);   // P(s)
        float4 v = reinterpret_cast<const float4*>(
            w + ((long)e * Oq + nb * 128 + ps) * Iq)[c4];
        uint4 p = make_uint4(f2tf32(v.x), f2tf32(v.y), f2tf32(v.z), f2tf32(v.w));
        reinterpret_cast<uint4*>(g_wprep)[row * 32 + c4] = p;
    }
}

// ---------------------------------------------------------------------------
// Persistent fused kernel, 2 CTAs/SM.  296 CTAs x 256 threads
// (8 warps: 4m x 2n, warp tile 32x64), tile 128x128, 3-buffer cp.async ring
// (fetch-ahead 2, one __syncthreads per stage).  B comes pre-rounded and
// pre-permuted from g_wprep: no gather math, no Bf rounding IADDs.
// Zero stores issued early; fence + monotonic barrier deferred to the first
// atomic scatter.  A fragments rounded with +0x1000 (tf32 RN at truncation).
// Tile t: n_base=(t&1)*128, m0=((t>>1)&7)*128, be=t>>4.
// ---------------------------------------------------------------------------
extern "C" __global__ void __launch_bounds__(NTHREADS, 2)
moe_persistent(const float* __restrict__ x,
               const int*   __restrict__ idx,
               const float* __restrict__ gate,
               const float* __restrict__ bias,
               float* __restrict__ out) {
    extern __shared__ char smem[];
    const uint32_t sbase = smem_u32(smem);
    const int tid  = threadIdx.x;
    const int wid  = tid >> 5;
    const int lane = tid & 31;
    const int cta  = blockIdx.x;

    // --- Per-thread cp.async geometry (tile-invariant) ---
    const int rt  = tid >> 3;             // 0..31
    const int c4l = tid & 7;
    const uint32_t swz = (uint32_t)((c4l ^ (rt & 7)) << 4);

    // --- Warp/lane geometry: 8 warps (4m x 2n), warp tile 32x64 ---
    const int m_w = (wid >> 1) * 32;
    const int n_w = (wid & 1) * 64;
    const int sub = lane >> 3;
    const int l7  = lane & 7;
    const int a_r[2] = { m_w + (sub & 1) * 8 + l7, m_w + 16 + (sub & 1) * 8 + l7 };
    const int a_kh = sub >> 1;
    const int b_kh = sub & 1;
    int b_n[4];
    #pragma unroll
    for (int jp = 0; jp < 4; jp++) b_n[jp] = n_w + jp * 16 + (sub >> 1) * 8 + l7;
    const int qrow = lane >> 2;
    const int colq = (lane & 3) * 4;

    // --- Prologue: issue chunks 0,1 of first tile into buffers 0,1 ---
    const int t0 = cta;
    const float* xb = x + ((long)(t0 >> 4) * Cq + ((t0 >> 1) & 7) * 128) * Iq;
    const float* wb = g_wprep + (long)(((t0 >> 4) & 7) * 2 + (t0 & 1)) * 128 * Iq;
    #pragma unroll
    for (int st = 0; st < 2; st++) {
        uint32_t aB = sbase + SMEM_TILES + st * STAGE_BYTES;
        uint32_t bB = aB + STAGE_A;
        #pragma unroll
        for (int i = 0; i < 4; i++) {
            int r = rt + i * 32;
            uint32_t soff = (uint32_t)(r * 128) + swz;
            CP_ASYNC16(aB + soff, xb + r * Iq + st * BK + c4l * 4);
            CP_ASYNC16(bB + soff, wb + r * Iq + st * BK + c4l * 4);
        }
        asm volatile("cp.async.commit_group;" ::: "memory");
    }

    // bias cache
    if (tid < 256) reinterpret_cast<float*>(smem + SMEM_BIAS)[tid] = bias[tid];

    // --- Issue zero stores (fire-and-forget; fence deferred) ---
    {
        float4* o4 = reinterpret_cast<float4*>(out);
        const int n4 = (Bq * Tq * Oq) / 4;
        float4 z = make_float4(0.f, 0.f, 0.f, 0.f);
        for (int i = cta * NTHREADS + tid; i < n4; i += NCTAS * NTHREADS)
            o4[i] = z;
    }

    // --- Persistent tile loop ---
    bool waited = false;
    int buf = 0;
    for (int t = t0; t < NTILES; t += NCTAS) {
        const int n_base = (t & 1) * 128;
        const int m0     = ((t >> 1) & 7) * 128;
        const int be     = t >> 4;
        const int b      = be >> 3;
        xb = x + ((long)be * Cq + m0) * Iq;
        wb = g_wprep + (long)((be & 7) * 2 + (t & 1)) * 128 * Iq;

        const int tn = t + NCTAS;
        const float* xb_n = xb;
        const float* wb_n = wb;
        if (tn < NTILES) {
            xb_n = x + ((long)(tn >> 4) * Cq + ((tn >> 1) & 7) * 128) * Iq;
            wb_n = g_wprep + (long)(((tn >> 4) & 7) * 2 + (tn & 1)) * 128 * Iq;
        }

        // gate/idx for epilogue (issued early)
        float g_r[4];
        int   tok_r[4];
        #pragma unroll
        for (int k = 0; k < 4; k++) {
            int r = m_w + k * 8 + qrow;
            g_r[k]   = gate[(long)be * Cq + m0 + r];
            tok_r[k] = idx [(long)be * Cq + m0 + r];
        }

        float acc[2][8][4];
        #pragma unroll
        for (int i = 0; i < 2; i++)
            #pragma unroll
            for (int j = 0; j < 8; j++)
                #pragma unroll
                for (int q = 0; q < 4; q++) acc[i][j][q] = 0.f;

        #pragma unroll
        for (int ks = 0; ks < 4; ks++) {
            asm volatile("cp.async.wait_group 1;" ::: "memory");
            __syncthreads();

            // Refill chunk ks+2 into buffer (buf+2)%3 (freed last stage).
            {
                const int fk = ks + 2;
                const float* rx = (fk < 4) ? xb : xb_n;
                const float* rw = (fk < 4) ? wb : wb_n;
                const int rks = fk & 3;
                int rbuf = buf + 2; if (rbuf >= NSTAGE) rbuf -= NSTAGE;
                uint32_t aB = sbase + SMEM_TILES + rbuf * STAGE_BYTES;
                uint32_t bB = aB + STAGE_A;
                #pragma unroll
                for (int i = 0; i < 4; i++) {
                    int r = rt + i * 32;
                    uint32_t soff = (uint32_t)(r * 128) + swz;
                    CP_ASYNC16(aB + soff, rx + r * Iq + rks * BK + c4l * 4);
                    CP_ASYNC16(bB + soff, rw + r * Iq + rks * BK + c4l * 4);
                }
                asm volatile("cp.async.commit_group;" ::: "memory");
            }

            // Compute chunk ks from buffer buf
            const uint32_t aB = sbase + SMEM_TILES + buf * STAGE_BYTES;
            const uint32_t bB = aB + STAGE_A;
            #pragma unroll
            for (int kk = 0; kk < 4; kk++) {
                uint32_t Af[2][4], Bf[4][4];
                #pragma unroll
                for (int i = 0; i < 2; i++) {
                    uint32_t chunk = (uint32_t)((kk * 2 + a_kh) ^ l7);
                    LDSM_X4(Af[i][0], Af[i][1], Af[i][2], Af[i][3],
                            aB + a_r[i] * 128 + (chunk << 4));
                }
                #pragma unroll
                for (int jp = 0; jp < 4; jp++) {
                    uint32_t chunk = (uint32_t)((kk * 2 + b_kh) ^ l7);
                    LDSM_X4(Bf[jp][0], Bf[jp][1], Bf[jp][2], Bf[jp][3],
                            bB + b_n[jp] * 128 + (chunk << 4));
                }
                // A-only tf32 round-to-nearest (B pre-rounded in g_wprep)
                #pragma unroll
                for (int i = 0; i < 2; i++)
                    #pragma unroll
                    for (int q = 0; q < 4; q++) Af[i][q] += 0x1000u;
                #pragma unroll
                for (int i = 0; i < 2; i++)
                    #pragma unroll
                    for (int j = 0; j < 8; j++)
                        MMA_TF32(acc[i][j], Af[i], Bf[j >> 1][(j & 1) * 2],
                                 Bf[j >> 1][(j & 1) * 2 + 1]);
            }
            buf = buf + 1; if (buf >= NSTAGE) buf = 0;
        }

        // Before the FIRST scatter: fence own zero stores, arrive, wait all.
        if (!waited) {
            __threadfence();
            __syncthreads();
            if (tid == 0) {
                unsigned tk;
                asm volatile("atom.add.release.gpu.u32 %0, [%1], %2;"
                             : "=r"(tk) : "l"(&g_zero_ctr), "r"(1u) : "memory");
                unsigned bar_target = (tk / NCTAS + 1) * NCTAS;
                unsigned v;
                do {
                    asm volatile("ld.acquire.gpu.u32 %0, [%1];"
                                 : "=r"(v) : "l"(&g_zero_ctr) : "memory");
                } while (v < bar_target);
            }
            __syncthreads();
            waited = true;
        }

        // --- Epilogue: bias + gate + red.v4 scatter (permuted-B layout) ---
        const float* bias_s = reinterpret_cast<const float*>(smem + SMEM_BIAS);
        #pragma unroll
        for (int i = 0; i < 2; i++) {
            #pragma unroll
            for (int half = 0; half < 2; half++) {
                const int k = i * 2 + half;
                float g = g_r[k];
                float* orow = out + ((long)b * Tq + tok_r[k]) * Oq;
                #pragma unroll
                for (int jj = 0; jj < 4; jj++) {
                    int col = n_base + ((n_w >> 4) + jj) * 16 + colq;
                    float4 bv = *reinterpret_cast<const float4*>(bias_s + col);
                    float v0 = (acc[i][2 * jj + 0][half * 2 + 0] + bv.x) * g;
                    float v1 = (acc[i][2 * jj + 1][half * 2 + 0] + bv.y) * g;
                    float v2 = (acc[i][2 * jj + 0][half * 2 + 1] + bv.z) * g;
                    float v3 = (acc[i][2 * jj + 1][half * 2 + 1] + bv.w) * g;
                    asm volatile("red.global.add.v4.f32 [%0], {%1, %2, %3, %4};"
                                 :: "l"(orow + col), "f"(v0), "f"(v1), "f"(v2), "f"(v3)
                                 : "memory");
                }
            }
        }
    }
}

// ---------------------------------------------------------------------------
// kernel_launch
// Inputs: x_expert f32, expert_indices i32, expert_gate f32, weight f32,
//         bias f32, num_tokens i32 (unused)
// ---------------------------------------------------------------------------
extern "C" void kernel_launch(void* const* d_in, const int* in_sizes, int n_in,
                              void* d_out, int out_size) {
    const float* x    = (const float*)d_in[0];
    const int*   idx  = (const int*)  d_in[1];
    const float* gate = (const float*)d_in[2];
    const float* w    = (const float*)d_in[3];
    const float* bias = (const float*)d_in[4];
    float* out = (float*)d_out;

    prep_weights<<<64, 256>>>(w);

    cudaFuncSetAttribute(moe_persistent,
                         cudaFuncAttributeMaxDynamicSharedMemorySize, SMEM_TOTAL);
    moe_persistent<<<NCTAS, NTHREADS, SMEM_TOTAL>>>(x, idx, gate, bias, out);
}

// round 11
// speedup vs baseline: 1.0558x; 1.0558x over previous
#include <cuda_runtime.h>
#include <cstdint>

// Problem shapes (fixed)
#define Bq 8
#define Eq 8
#define Cq 1024
#define Iq 128
#define Oq 256
#define Tq 8192

#define NTHREADS 256
#define NCTAS 444                      // 3 persistent CTAs per SM (148 SMs)
#define NTILES 2048                    // 4 n x 8 m x 64 be;  tile = 128 x 64
#define BK 32
#define NSTAGE 3
#define STAGE_A (128 * BK * 4)         // 16384
#define STAGE_Bb (64 * BK * 4)         // 8192
#define STAGE_BYTES (STAGE_A + STAGE_Bb)               // 24576
#define SMEM_BIAS  0
#define SMEM_TILES 1024
#define SMEM_TOTAL (SMEM_TILES + NSTAGE * STAGE_BYTES) // 74752 -> 3 CTAs/SM

// Monotonic arrival counter (never reset; generation = ticket/NCTAS).
__device__ unsigned int g_zero_ctr = 0;

__device__ __forceinline__ uint32_t smem_u32(const void* p) {
    uint32_t a;
    asm("{ .reg .u64 t; cvta.to.shared.u64 t, %1; cvt.u32.u64 %0, t; }"
        : "=r"(a) : "l"(p));
    return a;
}

#define CP_ASYNC16(saddr, gptr) \
    asm volatile("cp.async.cg.shared.global [%0], [%1], 16;" \
                 :: "r"(saddr), "l"(gptr) : "memory")

#define LDSM_X4(r0, r1, r2, r3, addr) \
    asm volatile("ldmatrix.sync.aligned.m8n8.x4.shared.b16 {%0,%1,%2,%3}, [%4];" \
                 : "=r"(r0), "=r"(r1), "=r"(r2), "=r"(r3) : "r"(addr))

#define MMA_TF32(c, a, b0, b1) \
    asm volatile("mma.sync.aligned.m16n8k8.row.col.f32.tf32.tf32.f32 " \
                 "{%0,%1,%2,%3}, {%4,%5,%6,%7}, {%8,%9}, {%0,%1,%2,%3};" \
                 : "+f"((c)[0]), "+f"((c)[1]), "+f"((c)[2]), "+f"((c)[3]) \
                 : "r"((a)[0]), "r"((a)[1]), "r"((a)[2]), "r"((a)[3]), \
                   "r"(b0), "r"(b1))

// ---------------------------------------------------------------------------
// Persistent fused kernel, 3 CTAs/SM (RF-fitting 128x64 tiles).
// 444 CTAs x 256 threads (8 warps: 4m x 2n, warp tile 32x32).
// 3-buffer cp.async ring, fetch-ahead 2, ONE __syncthreads per stage.
// Zero stores issued early (no fence); fence + monotonic barrier deferred to
// just before the first atomic scatter.
// B smem row s holds weight row P(s)=((s>>4)<<4)+((s&7)<<1)+((s>>3)&1)
// -> contiguous per-thread 4-col groups -> red.global.add.v4.f32.
// tf32 round-to-nearest: +0x1000 on raw f32 fragments before MMA.
// Tile t: n_base=(t&3)*64, m0=((t>>2)&7)*128, be=t>>5.
// ---------------------------------------------------------------------------
extern "C" __global__ void __launch_bounds__(NTHREADS, 3)
moe_persistent(const float* __restrict__ x,
               const int*   __restrict__ idx,
               const float* __restrict__ gate,
               const float* __restrict__ w,
               const float* __restrict__ bias,
               float* __restrict__ out) {
    extern __shared__ char smem[];
    const uint32_t sbase = smem_u32(smem);
    const int tid  = threadIdx.x;
    const int wid  = tid >> 5;
    const int lane = tid & 31;
    const int cta  = blockIdx.x;

    // --- Per-thread cp.async geometry (tile-invariant) ---
    // Per stage: A = 128 rows x 8 c4 (4 rows/thread), B = 64 rows (2 rows/thread)
    const int rt  = tid >> 3;             // 0..31
    const int c4l = tid & 7;
    const uint32_t swz = (uint32_t)((c4l ^ (rt & 7)) << 4);
    int prB[2];
    #pragma unroll
    for (int i = 0; i < 2; i++) {
        int s = rt + i * 32;
        prB[i] = ((s >> 4) << 4) + ((s & 7) << 1) + ((s >> 3) & 1);   // P(s)
    }

    // --- Warp/lane geometry: 8 warps (4m x 2n), warp tile 32x32 ---
    const int m_w = (wid >> 1) * 32;
    const int n_w = (wid & 1) * 32;
    const int sub = lane >> 3;
    const int l7  = lane & 7;
    const int a_r[2] = { m_w + (sub & 1) * 8 + l7, m_w + 16 + (sub & 1) * 8 + l7 };
    const int a_kh = sub >> 1;
    const int b_kh = sub & 1;
    const int b_n[2] = { n_w + (sub >> 1) * 8 + l7, n_w + 16 + (sub >> 1) * 8 + l7 };
    const int qrow = lane >> 2;
    const int colq = (lane & 3) * 4;

    // --- Prologue: issue chunks 0,1 of first tile into buffers 0,1 ---
    const int t0 = cta;
    const float* xb = x + ((long)(t0 >> 5) * Cq + ((t0 >> 2) & 7) * 128) * Iq;
    const float* wb = w + ((long)((t0 >> 5) & 7) * Oq + (t0 & 3) * 64) * Iq;
    #pragma unroll
    for (int st = 0; st < 2; st++) {
        uint32_t aB = sbase + SMEM_TILES + st * STAGE_BYTES;
        uint32_t bB = aB + STAGE_A;
        #pragma unroll
        for (int i = 0; i < 4; i++) {
            int r = rt + i * 32;
            CP_ASYNC16(aB + (uint32_t)(r * 128) + swz, xb + r * Iq + st * BK + c4l * 4);
        }
        #pragma unroll
        for (int i = 0; i < 2; i++) {
            int r = rt + i * 32;
            CP_ASYNC16(bB + (uint32_t)(r * 128) + swz, wb + prB[i] * Iq + st * BK + c4l * 4);
        }
        asm volatile("cp.async.commit_group;" ::: "memory");
    }

    // bias cache (256 threads, 256 floats)
    reinterpret_cast<float*>(smem + SMEM_BIAS)[tid] = bias[tid];

    // --- Issue zero stores (fire-and-forget; fence deferred) ---
    {
        float4* o4 = reinterpret_cast<float4*>(out);
        const int n4 = (Bq * Tq * Oq) / 4;
        float4 z = make_float4(0.f, 0.f, 0.f, 0.f);
        for (int i = cta * NTHREADS + tid; i < n4; i += NCTAS * NTHREADS)
            o4[i] = z;
    }

    // --- Persistent tile loop ---
    bool waited = false;
    int buf = 0;
    for (int t = t0; t < NTILES; t += NCTAS) {
        const int n_base = (t & 3) * 64;
        const int m0     = ((t >> 2) & 7) * 128;
        const int be     = t >> 5;
        const int b      = be >> 3;
        xb = x + ((long)be * Cq + m0) * Iq;
        wb = w + ((long)(be & 7) * Oq + n_base) * Iq;

        const int tn = t + NCTAS;
        const float* xb_n = xb;
        const float* wb_n = wb;
        if (tn < NTILES) {
            xb_n = x + ((long)(tn >> 5) * Cq + ((tn >> 2) & 7) * 128) * Iq;
            wb_n = w + ((long)((tn >> 5) & 7) * Oq + (tn & 3) * 64) * Iq;
        }

        // gate/idx for epilogue (issued early)
        float g_r[4];
        int   tok_r[4];
        #pragma unroll
        for (int k = 0; k < 4; k++) {
            int r = m_w + k * 8 + qrow;
            g_r[k]   = gate[(long)be * Cq + m0 + r];
            tok_r[k] = idx [(long)be * Cq + m0 + r];
        }

        float acc[2][4][4];
        #pragma unroll
        for (int i = 0; i < 2; i++)
            #pragma unroll
            for (int j = 0; j < 4; j++)
                #pragma unroll
                for (int q = 0; q < 4; q++) acc[i][j][q] = 0.f;

        #pragma unroll
        for (int ks = 0; ks < 4; ks++) {
            asm volatile("cp.async.wait_group 1;" ::: "memory");
            __syncthreads();

            // Refill chunk ks+2 into buffer (buf+2)%3 (freed last stage).
            {
                const int fk = ks + 2;
                const float* rx = (fk < 4) ? xb : xb_n;
                const float* rw = (fk < 4) ? wb : wb_n;
                const int rks = fk & 3;
                int rbuf = buf + 2; if (rbuf >= NSTAGE) rbuf -= NSTAGE;
                uint32_t aB = sbase + SMEM_TILES + rbuf * STAGE_BYTES;
                uint32_t bB = aB + STAGE_A;
                #pragma unroll
                for (int i = 0; i < 4; i++) {
                    int r = rt + i * 32;
                    CP_ASYNC16(aB + (uint32_t)(r * 128) + swz,
                               rx + r * Iq + rks * BK + c4l * 4);
                }
                #pragma unroll
                for (int i = 0; i < 2; i++) {
                    int r = rt + i * 32;
                    CP_ASYNC16(bB + (uint32_t)(r * 128) + swz,
                               rw + prB[i] * Iq + rks * BK + c4l * 4);
                }
                asm volatile("cp.async.commit_group;" ::: "memory");
            }

            // Compute chunk ks from buffer buf
            const uint32_t aB = sbase + SMEM_TILES + buf * STAGE_BYTES;
            const uint32_t bB = aB + STAGE_A;
            #pragma unroll
            for (int kk = 0; kk < 4; kk++) {
                uint32_t Af[2][4], Bf[2][4];
                #pragma unroll
                for (int i = 0; i < 2; i++) {
                    uint32_t chunk = (uint32_t)((kk * 2 + a_kh) ^ l7);
                    LDSM_X4(Af[i][0], Af[i][1], Af[i][2], Af[i][3],
                            aB + a_r[i] * 128 + (chunk << 4));
                }
                #pragma unroll
                for (int jp = 0; jp < 2; jp++) {
                    uint32_t chunk = (uint32_t)((kk * 2 + b_kh) ^ l7);
                    LDSM_X4(Bf[jp][0], Bf[jp][1], Bf[jp][2], Bf[jp][3],
                            bB + b_n[jp] * 128 + (chunk << 4));
                }
                // tf32 round-to-nearest at the truncation boundary
                #pragma unroll
                for (int i = 0; i < 2; i++)
                    #pragma unroll
                    for (int q = 0; q < 4; q++) {
                        Af[i][q] += 0x1000u;
                        Bf[i][q] += 0x1000u;
                    }
                #pragma unroll
                for (int i = 0; i < 2; i++)
                    #pragma unroll
                    for (int j = 0; j < 4; j++)
                        MMA_TF32(acc[i][j], Af[i], Bf[j >> 1][(j & 1) * 2],
                                 Bf[j >> 1][(j & 1) * 2 + 1]);
            }
            buf = buf + 1; if (buf >= NSTAGE) buf = 0;
        }

        // Before the FIRST scatter: fence own zero stores, arrive, wait all.
        if (!waited) {
            __threadfence();
            __syncthreads();
            if (tid == 0) {
                unsigned tk;
                asm volatile("atom.add.release.gpu.u32 %0, [%1], %2;"
                             : "=r"(tk) : "l"(&g_zero_ctr), "r"(1u) : "memory");
                unsigned bar_target = (tk / NCTAS + 1) * NCTAS;
                unsigned v;
                do {
                    asm volatile("ld.acquire.gpu.u32 %0, [%1];"
                                 : "=r"(v) : "l"(&g_zero_ctr) : "memory");
                } while (v < bar_target);
            }
            __syncthreads();
            waited = true;
        }

        // --- Epilogue: bias + gate + red.v4 scatter (permuted-B layout) ---
        const float* bias_s = reinterpret_cast<const float*>(smem + SMEM_BIAS);
        #pragma unroll
        for (int i = 0; i < 2; i++) {
            #pragma unroll
            for (int half = 0; half < 2; half++) {
                const int k = i * 2 + half;
                float g = g_r[k];
                float* orow = out + ((long)b * Tq + tok_r[k]) * Oq;
                #pragma unroll
                for (int jj = 0; jj < 2; jj++) {
                    int col = n_base + ((n_w >> 4) + jj) * 16 + colq;
                    float4 bv = *reinterpret_cast<const float4*>(bias_s + col);
                    float v0 = (acc[i][2 * jj + 0][half * 2 + 0] + bv.x) * g;
                    float v1 = (acc[i][2 * jj + 1][half * 2 + 0] + bv.y) * g;
                    float v2 = (acc[i][2 * jj + 0][half * 2 + 1] + bv.z) * g;
                    float v3 = (acc[i][2 * jj + 1][half * 2 + 1] + bv.w) * g;
                    asm volatile("red.global.add.v4.f32 [%0], {%1, %2, %3, %4};"
                                 :: "l"(orow + col), "f"(v0), "f"(v1), "f"(v2), "f"(v3)
                                 : "memory");
                }
            }
        }
    }
}

// ---------------------------------------------------------------------------
// kernel_launch
// Inputs: x_expert f32, expert_indices i32, expert_gate f32, weight f32,
//         bias f32, num_tokens i32 (unused)
// ---------------------------------------------------------------------------
extern "C" void kernel_launch(void* const* d_in, const int* in_sizes, int n_in,
                              void* d_out, int out_size) {
    const float* x    = (const float*)d_in[0];
    const int*   idx  = (const int*)  d_in[1];
    const float* gate = (const float*)d_in[2];
    const float* w    = (const float*)d_in[3];
    const float* bias = (const float*)d_in[4];
    float* out = (float*)d_out;

    cudaFuncSetAttribute(moe_persistent,
                         cudaFuncAttributeMaxDynamicSharedMemorySize, SMEM_TOTAL);
    moe_persistent<<<NCTAS, NTHREADS, SMEM_TOTAL>>>(x, idx, gate, w, bias, out);
}